// round 7
// baseline (speedup 1.0000x reference)
#include <cuda_runtime.h>
#include <cstdint>
#include <cstddef>

// ---------------- problem constants ----------------
#define BN_   8
#define C_    512
#define H0_   32
#define W0_   32
#define CV_   256

// output layout: masks (8*1*128*128) | logits (8*23) | src (8*512*32*32)
#define MASK_OFF   0
#define LOGIT_OFF  131072
#define SRC_OFF    131256

// ---------------- scratch (device globals; no runtime alloc) ----------------
__device__ float g_X  [C_ * BN_ * H0_ * W0_];            // [c][b*1024+n] = img + pe
__device__ float g_src[C_ * BN_ * H0_ * W0_];            // [d][b*1024+n]
__device__ float g_x1 [512 * 8 * 64 * 64];               // up2x(src)        [c][b][64][64]
__device__ float g_c1 [512 * 8 * 64 * 64];               // conv1 out / bnrelu
__device__ float g_x2 [512 * 8 * 128 * 128];             // up2x(c1)
__device__ float g_c2 [256 * 8 * 128 * 128];             // conv2 out / bnrelu
__device__ float g_c3 [256 * 8 * 128 * 128];             // conv3 out (+bias)
__device__ float g_ans   [8 * 512];
__device__ float g_ansvec[8 * 512];
__device__ float g_qa    [8 * 1024];
__device__ float g_word  [8 * 512];
__device__ float g_dyn   [8 * 2305];
__device__ float g_hidden[8 * 256];
__device__ float g_gates [8 * 8];
__device__ float g_feat  [8 * 128];
__device__ float g_mv1   [2 * 512];                      // mean | rstd (conv1)
__device__ float g_mv2   [2 * 256];                      // mean | rstd (conv2)

// ---------------- helpers ----------------
__device__ __forceinline__ float blockReduceSum(float v, float* sh) {
    int tid = threadIdx.x;
    sh[tid] = v; __syncthreads();
    for (int off = blockDim.x >> 1; off > 0; off >>= 1) {
        if (tid < off) sh[tid] += sh[tid + off];
        __syncthreads();
    }
    return sh[0];
}

// ---------------- stage 0: X = img + positional encoding, layout [c][ng] ----------------
__global__ void k_build_x(const float* __restrict__ img) {
    size_t idx = (size_t)blockIdx.x * 256 + threadIdx.x;   // total 512*8192
    int ng = (int)(idx & 8191);
    int c  = (int)(idx >> 13);
    int b  = ng >> 10;
    int n  = ng & 1023;
    int h  = n >> 5, w = n & 31;

    int i; float pos;
    if (c < 256) { i = c >> 1;          pos = (float)w; }
    else         { i = (c - 256) >> 1;  pos = (float)h; }
    float freq = expf(-(float)(2 * i) * (9.210340371976184f / 256.f));  // ln(1e4)/256
    float ang  = pos * freq;
    float pe   = (c & 1) ? cosf(ang) : sinf(ang);

    g_X[idx] = img[((size_t)b * 512 + c) * 1024 + n] + pe;
}

// ---------------- generic fp32 implicit-GEMM conv: O[co][pos] = A[co][:] . im2col ----------------
// KS==1: plain GEMM (X is [k][pos]); KS==3: 3x3 pad=1, X is [ci][b][H][W]
template <int KS>
__global__ void __launch_bounds__(256)
conv_gemm(const float* __restrict__ A, const float* __restrict__ X,
          const float* __restrict__ bias, float* __restrict__ O,
          int Ci, int H, int W, int Bn, int Npos)
{
    const int K = Ci * KS * KS;
    __shared__ float As[8][132];
    __shared__ float Bs[8][132];

    int tid     = threadIdx.x;
    int coBase  = blockIdx.y * 128;
    int posBase = blockIdx.x * 128;

    int lane = tid & 127;
    int lpos = posBase + lane;
    int bk   = tid >> 7;
    int b_b = 0, b_oh = 0, b_ow = 0;
    if (KS == 3) { b_ow = lpos % W; int t = lpos / W; b_oh = t % H; b_b = t / H; }
    const int HW = H * W;

    int ar = tid >> 1;
    int ak = (tid & 1) * 4;
    const float* Arow = A + (size_t)(coBase + ar) * K + ak;

    float acc[8][8];
#pragma unroll
    for (int i = 0; i < 8; i++)
#pragma unroll
        for (int j = 0; j < 8; j++) acc[i][j] = 0.f;

    int tx = tid & 15;
    int ty = tid >> 4;

    for (int kc = 0; kc < K; kc += 8) {
        float4 av = *(const float4*)(Arow + kc);
        float bv[4];
#pragma unroll
        for (int j = 0; j < 4; j++) {
            int k = kc + bk + 2 * j;
            float v;
            if (KS == 3) {
                int ci = k / 9;
                int t  = k - ci * 9;
                int dy = t / 3;
                int dx = t - dy * 3;
                int ih = b_oh + dy - 1;
                int iw = b_ow + dx - 1;
                v = 0.f;
                if ((unsigned)ih < (unsigned)H && (unsigned)iw < (unsigned)W)
                    v = X[((size_t)ci * Bn + b_b) * HW + ih * W + iw];
            } else {
                v = X[(size_t)k * Npos + lpos];
            }
            bv[j] = v;
        }
        As[ak + 0][ar] = av.x; As[ak + 1][ar] = av.y;
        As[ak + 2][ar] = av.z; As[ak + 3][ar] = av.w;
#pragma unroll
        for (int j = 0; j < 4; j++) Bs[bk + 2 * j][lane] = bv[j];
        __syncthreads();

#pragma unroll
        for (int kk = 0; kk < 8; kk++) {
            float a[8], bb[8];
            *(float4*)&a[0]  = *(const float4*)&As[kk][ty * 4];
            *(float4*)&a[4]  = *(const float4*)&As[kk][64 + ty * 4];
            *(float4*)&bb[0] = *(const float4*)&Bs[kk][tx * 4];
            *(float4*)&bb[4] = *(const float4*)&Bs[kk][64 + tx * 4];
#pragma unroll
            for (int i = 0; i < 8; i++)
#pragma unroll
                for (int j = 0; j < 8; j++)
                    acc[i][j] += a[i] * bb[j];
        }
        __syncthreads();
    }

#pragma unroll
    for (int i = 0; i < 8; i++) {
        int coOff = (i < 4) ? (ty * 4 + i) : (64 + ty * 4 + i - 4);
        int co = coBase + coOff;
        float bs = bias ? bias[co] : 0.f;
        float4 v0, v1;
        v0.x = acc[i][0] + bs; v0.y = acc[i][1] + bs; v0.z = acc[i][2] + bs; v0.w = acc[i][3] + bs;
        v1.x = acc[i][4] + bs; v1.y = acc[i][5] + bs; v1.z = acc[i][6] + bs; v1.w = acc[i][7] + bs;
        *(float4*)&O[(size_t)co * Npos + posBase + tx * 4]      = v0;
        *(float4*)&O[(size_t)co * Npos + posBase + 64 + tx * 4] = v1;
    }
}

// ---------------- src copy to d_out (NCHW) ----------------
__global__ void k_src_copy(float* __restrict__ out) {
    size_t idx = (size_t)blockIdx.x * 256 + threadIdx.x;   // 4,194,304
    int d  = (int)(idx >> 13);
    int ng = (int)(idx & 8191);
    int b  = ng >> 10;
    int n  = ng & 1023;
    out[SRC_OFF + ((size_t)(b * 512 + d)) * 1024 + n] = g_src[idx];
}

// ---------------- ans = mean(src, HW) ----------------
__global__ void k_ans() {
    __shared__ float sh[128];
    int id = blockIdx.x;           // d*8+b
    int d = id >> 3, b = id & 7;
    const float* p = g_src + (size_t)d * 8192 + b * 1024;
    float s = 0.f;
    for (int i = threadIdx.x; i < 1024; i += 128) s += p[i];
    s = blockReduceSum(s, sh);
    if (threadIdx.x == 0) g_ans[b * 512 + d] = s * (1.f / 1024.f);
}

// ---------------- ans_vec = ans @ ln_ans_w^T + b ----------------
__global__ void k_ansvec(const float* __restrict__ w, const float* __restrict__ bias) {
    __shared__ float sh[128];
    int b = blockIdx.x >> 9;
    int d = blockIdx.x & 511;
    float s = 0.f;
    for (int c = threadIdx.x; c < 512; c += 128)
        s += g_ans[b * 512 + c] * w[(size_t)d * 512 + c];
    s = blockReduceSum(s, sh);
    if (threadIdx.x == 0) g_ansvec[b * 512 + d] = s + bias[d];
}

// ---------------- qa build + softmax*qa fold to word ----------------
__global__ void k_qa_word(const float* __restrict__ state) {
    int b = blockIdx.x, tid = threadIdx.x;
    __shared__ float sh[256];
    float* qa = g_qa + b * 1024;
    for (int i = tid; i < 1024; i += 256) {
        float v = (i < 512) ? state[b * 512 + i] : g_ansvec[b * 512 + (i - 512)];
        qa[i] = v;
    }
    __syncthreads();
    float mx = -1e30f;
    for (int i = tid; i < 1024; i += 256) mx = fmaxf(mx, qa[i]);
    sh[tid] = mx; __syncthreads();
    for (int off = 128; off; off >>= 1) { if (tid < off) sh[tid] = fmaxf(sh[tid], sh[tid + off]); __syncthreads(); }
    mx = sh[0]; __syncthreads();
    float s = 0.f;
    for (int i = tid; i < 1024; i += 256) s += expf(qa[i] - mx);
    s = blockReduceSum(s, sh);
    float inv = 1.f / s;
    for (int c = tid; c < 512; c += 256) {
        float q1 = qa[c], q2 = qa[c + 512];
        g_word[b * 512 + c] = expf(q1 - mx) * inv * q1 + expf(q2 - mx) * inv * q2;
    }
}

// ---------------- dyn weights: word @ txt_w^T + txt_b ----------------
__global__ void k_dyngemm(const float* __restrict__ w, const float* __restrict__ bias) {
    __shared__ float sh[128];
    int j = blockIdx.x, b = blockIdx.y;
    float s = 0.f;
    for (int c = threadIdx.x; c < 512; c += 128)
        s += g_word[b * 512 + c] * w[(size_t)j * 512 + c];
    s = blockReduceSum(s, sh);
    if (threadIdx.x == 0) g_dyn[b * 2305 + j] = s + bias[j];
}

// ---------------- router stage 1 ----------------
__global__ void k_router1(const float* __restrict__ w1, const float* __restrict__ b1) {
    __shared__ float sh[128];
    int i = blockIdx.x, b = blockIdx.y;
    float s = 0.f;
    for (int c = threadIdx.x; c < 1024; c += 128)
        s += g_qa[b * 1024 + c] * w1[(size_t)i * 1024 + c];
    s = blockReduceSum(s, sh);
    if (threadIdx.x == 0) { float v = s + b1[i]; g_hidden[b * 256 + i] = v > 0.f ? v : 0.f; }
}

// ---------------- router stage 2 + softmax gates ----------------
__global__ void k_gates(const float* __restrict__ w2, const float* __restrict__ b2) {
    int b = blockIdx.x, t = threadIdx.x;   // 32 threads
    float v = -1e30f;
    if (t < 8) {
        float s = b2[t];
        for (int i = 0; i < 256; i++) s += g_hidden[b * 256 + i] * w2[t * 256 + i];
        v = s;
    }
    float mx = v;
    for (int off = 4; off; off >>= 1) mx = fmaxf(mx, __shfl_xor_sync(0xffffffffu, mx, off));
    float e = (t < 8) ? expf(v - mx) : 0.f;
    float s = e;
    for (int off = 4; off; off >>= 1) s += __shfl_xor_sync(0xffffffffu, s, off);
    if (t < 8) g_gates[b * 8 + t] = e / s;
}

// ---------------- feat128 ----------------
__global__ void k_feat(const float* __restrict__ w, const float* __restrict__ bias) {
    __shared__ float sh[128];
    int f = blockIdx.x, b = blockIdx.y;
    float s = 0.f;
    for (int c = threadIdx.x; c < 512; c += 128)
        s += g_ansvec[b * 512 + c] * w[(size_t)f * 512 + c];
    s = blockReduceSum(s, sh);
    if (threadIdx.x == 0) g_feat[b * 128 + f] = s + bias[f];
}

// ---------------- expert logits ----------------
__global__ void k_logits(const float* __restrict__ ew, const float* __restrict__ eb,
                         float* __restrict__ out) {
    int b = blockIdx.x, t = threadIdx.x;   // 192 threads
    __shared__ float sh[184];
    if (t < 184) {
        int o = t >> 3, e = t & 7;
        const float* w = ew + ((size_t)e * 23 + o) * 128;
        float s = 0.f;
        for (int f = 0; f < 128; f++) s += w[f] * g_feat[b * 128 + f];
        sh[t] = g_gates[b * 8 + e] * (s + eb[e * 23 + o]);
    }
    __syncthreads();
    if (t < 23) {
        float s = 0.f;
        for (int e = 0; e < 8; e++) s += sh[t * 8 + e];
        out[LOGIT_OFF + b * 23 + t] = s;
    }
}

// ---------------- bilinear 2x upsample (half-pixel centers, edge clamp) ----------------
__global__ void k_up2x(const float* __restrict__ in, float* __restrict__ outp,
                       int Hin, int logWout) {
    size_t idx = (size_t)blockIdx.x * 256 + threadIdx.x;
    int Wout = 1 << logWout;
    int ow = (int)(idx & (Wout - 1));
    int oh = (int)((idx >> logWout) & (Wout - 1));      // square tiles: Hout==Wout
    size_t cb = idx >> (2 * logWout);
    int Win = Hin;

    float fy = oh * 0.5f - 0.25f;
    float fx = ow * 0.5f - 0.25f;
    int y0 = (int)floorf(fy); float wy = fy - y0;
    int x0 = (int)floorf(fx); float wx = fx - x0;
    int y1 = y0 + 1, x1 = x0 + 1;
    y0 = max(y0, 0); y1 = min(y1, Hin - 1);
    x0 = max(x0, 0); x1 = min(x1, Win - 1);
    const float* p = in + cb * (size_t)(Hin * Win);
    float v00 = p[y0 * Win + x0], v01 = p[y0 * Win + x1];
    float v10 = p[y1 * Win + x0], v11 = p[y1 * Win + x1];
    outp[idx] = (1.f - wy) * ((1.f - wx) * v00 + wx * v01)
              +        wy  * ((1.f - wx) * v10 + wx * v11);
}

// ---------------- batchnorm statistics (per channel over B*H*W) ----------------
__global__ void k_bnstats(const float* __restrict__ X, float* __restrict__ mv, int Npix) {
    __shared__ float ss[256];
    __shared__ float sq[256];
    int c = blockIdx.x, tid = threadIdx.x;
    const float* p = X + (size_t)c * Npix;
    float s = 0.f, q = 0.f;
    for (int i = tid; i < Npix; i += 256) { float v = p[i]; s += v; q += v * v; }
    ss[tid] = s; sq[tid] = q; __syncthreads();
    for (int off = 128; off; off >>= 1) {
        if (tid < off) { ss[tid] += ss[tid + off]; sq[tid] += sq[tid + off]; }
        __syncthreads();
    }
    if (tid == 0) {
        float m   = ss[0] / Npix;
        float var = sq[0] / Npix - m * m;
        mv[c]              = m;
        mv[gridDim.x + c]  = rsqrtf(var + 1e-5f);
    }
}

// ---------------- bn + relu apply (in place) ----------------
__global__ void k_bnrelu(float* __restrict__ X, const float* __restrict__ mv,
                         const float* __restrict__ g, const float* __restrict__ bt,
                         int shift, int Cc) {
    size_t idx = (size_t)blockIdx.x * 256 + threadIdx.x;
    int c = (int)(idx >> shift);
    float y = (X[idx] - mv[c]) * mv[Cc + c] * g[c] + bt[c];
    X[idx] = y > 0.f ? y : 0.f;
}

// ---------------- dynamic per-batch 3x3 conv -> masks ----------------
__global__ void k_dynconv(float* __restrict__ out) {
    int b  = blockIdx.x;
    int r0 = blockIdx.y * 16;
    int tid = threadIdx.x;
    __shared__ float wsh[2304];
    __shared__ float insh[18 * 128];
    for (int i = tid; i < 2304; i += 256) wsh[i] = g_dyn[b * 2305 + i];
    float bias = g_dyn[b * 2305 + 2304];
    int ow   = tid & 127;
    int half = tid >> 7;
    float acc[8];
#pragma unroll
    for (int u = 0; u < 8; u++) acc[u] = bias;

    for (int ci = 0; ci < 256; ci++) {
        __syncthreads();
        for (int i = tid; i < 18 * 128; i += 256) {
            int rr = i >> 7, cc = i & 127;
            int ih = r0 - 1 + rr;
            insh[i] = (ih >= 0 && ih < 128)
                        ? g_c3[((size_t)ci * 8 + b) * 16384 + ih * 128 + cc] : 0.f;
        }
        __syncthreads();
        const float* wp = &wsh[ci * 9];
        float w0 = wp[0], w1 = wp[1], w2 = wp[2];
        float w3 = wp[3], w4 = wp[4], w5 = wp[5];
        float w6 = wp[6], w7 = wp[7], w8 = wp[8];
#pragma unroll
        for (int u = 0; u < 8; u++) {
            int orow = half + 2 * u;
            const float* ra = &insh[orow * 128];
            const float* rb = ra + 128;
            const float* rc = rb + 128;
            float a00 = (ow > 0)   ? ra[ow - 1] : 0.f, a01 = ra[ow], a02 = (ow < 127) ? ra[ow + 1] : 0.f;
            float a10 = (ow > 0)   ? rb[ow - 1] : 0.f, a11 = rb[ow], a12 = (ow < 127) ? rb[ow + 1] : 0.f;
            float a20 = (ow > 0)   ? rc[ow - 1] : 0.f, a21 = rc[ow], a22 = (ow < 127) ? rc[ow + 1] : 0.f;
            acc[u] += a00 * w0 + a01 * w1 + a02 * w2
                    + a10 * w3 + a11 * w4 + a12 * w5
                    + a20 * w6 + a21 * w7 + a22 * w8;
        }
    }
#pragma unroll
    for (int u = 0; u < 8; u++) {
        int orow = half + 2 * u;
        out[MASK_OFF + b * 16384 + (r0 + orow) * 128 + ow] = acc[u];
    }
}

// ---------------- launch ----------------
extern "C" void kernel_launch(void* const* d_in, const int* in_sizes, int n_in,
                              void* d_out, int out_size) {
    const float* img       = (const float*)d_in[0];
    const float* state     = (const float*)d_in[2];
    const float* W_t       = (const float*)d_in[4];
    const float* conv1_w   = (const float*)d_in[7];
    const float* bn1_g     = (const float*)d_in[8];
    const float* bn1_b     = (const float*)d_in[9];
    const float* conv2_w   = (const float*)d_in[10];
    const float* bn2_g     = (const float*)d_in[11];
    const float* bn2_b     = (const float*)d_in[12];
    const float* conv3_w   = (const float*)d_in[13];
    const float* conv3_b   = (const float*)d_in[14];
    const float* txt_w     = (const float*)d_in[15];
    const float* txt_b     = (const float*)d_in[16];
    const float* ln_ans_w  = (const float*)d_in[17];
    const float* ln_ans_b  = (const float*)d_in[18];
    const float* ln_ans2_w = (const float*)d_in[19];
    const float* ln_ans2_b = (const float*)d_in[20];
    const float* router_w1 = (const float*)d_in[21];
    const float* router_b1 = (const float*)d_in[22];
    const float* router_w2 = (const float*)d_in[23];
    const float* router_b2 = (const float*)d_in[24];
    const float* experts_w = (const float*)d_in[25];
    const float* experts_b = (const float*)d_in[26];
    float* out = (float*)d_out;

    float *pX, *pSrc, *pX1, *pC1, *pX2, *pC2, *pC3, *pMv1, *pMv2;
    cudaGetSymbolAddress((void**)&pX,   g_X);
    cudaGetSymbolAddress((void**)&pSrc, g_src);
    cudaGetSymbolAddress((void**)&pX1,  g_x1);
    cudaGetSymbolAddress((void**)&pC1,  g_c1);
    cudaGetSymbolAddress((void**)&pX2,  g_x2);
    cudaGetSymbolAddress((void**)&pC2,  g_c2);
    cudaGetSymbolAddress((void**)&pC3,  g_c3);
    cudaGetSymbolAddress((void**)&pMv1, g_mv1);
    cudaGetSymbolAddress((void**)&pMv2, g_mv2);

    // src path
    k_build_x<<<16384, 256>>>(img);
    conv_gemm<1><<<dim3(64, 4), 256>>>(W_t, pX, nullptr, pSrc, 512, 1, 1, 1, 8192);
    k_src_copy<<<16384, 256>>>(out);

    // token / small path
    k_ans<<<4096, 128>>>();
    k_ansvec<<<4096, 128>>>(ln_ans_w, ln_ans_b);
    k_qa_word<<<8, 256>>>(state);
    k_dyngemm<<<dim3(2305, 8), 128>>>(txt_w, txt_b);
    k_router1<<<dim3(256, 8), 128>>>(router_w1, router_b1);
    k_gates<<<8, 32>>>(router_w2, router_b2);
    k_feat<<<dim3(128, 8), 128>>>(ln_ans2_w, ln_ans2_b);
    k_logits<<<8, 192>>>(experts_w, experts_b, out);

    // vision path
    k_up2x<<<65536, 256>>>(pSrc, pX1, 32, 6);                                   // 32 -> 64
    conv_gemm<3><<<dim3(256, 4), 256>>>(conv1_w, pX1, nullptr, pC1, 512, 64, 64, 8, 32768);
    k_bnstats<<<512, 256>>>(pC1, pMv1, 32768);
    k_bnrelu<<<65536, 256>>>(pC1, pMv1, bn1_g, bn1_b, 15, 512);
    k_up2x<<<262144, 256>>>(pC1, pX2, 64, 7);                                   // 64 -> 128
    conv_gemm<3><<<dim3(1024, 2), 256>>>(conv2_w, pX2, nullptr, pC2, 512, 128, 128, 8, 131072);
    k_bnstats<<<256, 256>>>(pC2, pMv2, 131072);
    k_bnrelu<<<131072, 256>>>(pC2, pMv2, bn2_g, bn2_b, 17, 256);
    conv_gemm<1><<<dim3(1024, 2), 256>>>(conv3_w, pC2, conv3_b, pC3, 256, 1, 1, 1, 131072);

    // dynamic conv -> masks
    k_dynconv<<<dim3(8, 8), 256>>>(out);

    (void)in_sizes; (void)n_in; (void)out_size;
}

// round 8
// speedup vs baseline: 1.0488x; 1.0488x over previous
#include <cuda_runtime.h>
#include <cstdint>
#include <cstddef>

// ---------------- problem constants ----------------
#define BN_   8
#define C_    512
#define H0_   32
#define W0_   32
#define CV_   256

// output layout: masks (8*1*128*128) | logits (8*23) | src (8*512*32*32)
#define MASK_OFF   0
#define LOGIT_OFF  131072
#define SRC_OFF    131256

// ---------------- scratch (device globals; no runtime alloc) ----------------
__device__ float g_X  [C_ * BN_ * H0_ * W0_];            // [c][b*1024+n] = img + pe
__device__ float g_src[C_ * BN_ * H0_ * W0_];            // [d][b*1024+n]
__device__ float g_x1 [512 * 8 * 64 * 64];               // up2x(src)        [c][b][64][64]
__device__ float g_c1 [512 * 8 * 64 * 64];               // conv1 out / bnrelu
__device__ float g_x2 [512 * 8 * 128 * 128];             // up2x(c1)
__device__ float g_c2 [256 * 8 * 128 * 128];             // conv2 out / bnrelu
__device__ float g_c3 [256 * 8 * 128 * 128];             // conv3 out (+bias)
__device__ float g_ans   [8 * 512];
__device__ float g_ansvec[8 * 512];
__device__ float g_qa    [8 * 1024];
__device__ float g_word  [8 * 512];
__device__ float g_dyn   [8 * 2305];
__device__ float g_hidden[8 * 256];
__device__ float g_gates [8 * 8];
__device__ float g_feat  [8 * 128];
__device__ float g_mv1   [2 * 512];                      // mean | rstd (conv1)
__device__ float g_mv2   [2 * 256];                      // mean | rstd (conv2)

// ---------------- helpers ----------------
__device__ __forceinline__ float blockReduceSum(float v, float* sh) {
    int tid = threadIdx.x;
    sh[tid] = v; __syncthreads();
    for (int off = blockDim.x >> 1; off > 0; off >>= 1) {
        if (tid < off) sh[tid] += sh[tid + off];
        __syncthreads();
    }
    return sh[0];
}

// ---------------- stage 0: X = img + positional encoding, layout [c][ng] ----------------
__global__ void k_build_x(const float* __restrict__ img) {
    size_t idx = (size_t)blockIdx.x * 256 + threadIdx.x;   // total 512*8192
    int ng = (int)(idx & 8191);
    int c  = (int)(idx >> 13);
    int b  = ng >> 10;
    int n  = ng & 1023;
    int h  = n >> 5, w = n & 31;

    int i; float pos;
    if (c < 256) { i = c >> 1;          pos = (float)w; }
    else         { i = (c - 256) >> 1;  pos = (float)h; }
    float freq = expf(-(float)(2 * i) * (9.210340371976184f / 256.f));  // ln(1e4)/256
    float ang  = pos * freq;
    float pe   = (c & 1) ? cosf(ang) : sinf(ang);

    g_X[idx] = img[((size_t)b * 512 + c) * 1024 + n] + pe;
}

// ---------------- generic fp32 implicit-GEMM conv: O[co][pos] = A[co][:] . im2col ----------------
// KS==1: plain GEMM (X is [k][pos]); KS==3: 3x3 pad=1, X is [ci][b][H][W]
template <int KS>
__global__ void __launch_bounds__(256)
conv_gemm(const float* __restrict__ A, const float* __restrict__ X,
          const float* __restrict__ bias, float* __restrict__ O,
          int Ci, int H, int W, int Bn, int Npos)
{
    const int K = Ci * KS * KS;
    __shared__ float As[8][132];
    __shared__ float Bs[8][132];

    int tid     = threadIdx.x;
    int coBase  = blockIdx.y * 128;
    int posBase = blockIdx.x * 128;

    int lane = tid & 127;
    int lpos = posBase + lane;
    int bk   = tid >> 7;
    int b_b = 0, b_oh = 0, b_ow = 0;
    if (KS == 3) { b_ow = lpos % W; int t = lpos / W; b_oh = t % H; b_b = t / H; }
    const int HW = H * W;

    int ar = tid >> 1;
    int ak = (tid & 1) * 4;
    const float* Arow = A + (size_t)(coBase + ar) * K + ak;

    float acc[8][8];
#pragma unroll
    for (int i = 0; i < 8; i++)
#pragma unroll
        for (int j = 0; j < 8; j++) acc[i][j] = 0.f;

    int tx = tid & 15;
    int ty = tid >> 4;

    for (int kc = 0; kc < K; kc += 8) {
        float4 av = *(const float4*)(Arow + kc);
        float bv[4];
#pragma unroll
        for (int j = 0; j < 4; j++) {
            int k = kc + bk + 2 * j;
            float v;
            if (KS == 3) {
                int ci = k / 9;
                int t  = k - ci * 9;
                int dy = t / 3;
                int dx = t - dy * 3;
                int ih = b_oh + dy - 1;
                int iw = b_ow + dx - 1;
                v = 0.f;
                if ((unsigned)ih < (unsigned)H && (unsigned)iw < (unsigned)W)
                    v = X[((size_t)ci * Bn + b_b) * HW + ih * W + iw];
            } else {
                v = X[(size_t)k * Npos + lpos];
            }
            bv[j] = v;
        }
        As[ak + 0][ar] = av.x; As[ak + 1][ar] = av.y;
        As[ak + 2][ar] = av.z; As[ak + 3][ar] = av.w;
#pragma unroll
        for (int j = 0; j < 4; j++) Bs[bk + 2 * j][lane] = bv[j];
        __syncthreads();

#pragma unroll
        for (int kk = 0; kk < 8; kk++) {
            float a[8], bb[8];
            *(float4*)&a[0]  = *(const float4*)&As[kk][ty * 4];
            *(float4*)&a[4]  = *(const float4*)&As[kk][64 + ty * 4];
            *(float4*)&bb[0] = *(const float4*)&Bs[kk][tx * 4];
            *(float4*)&bb[4] = *(const float4*)&Bs[kk][64 + tx * 4];
#pragma unroll
            for (int i = 0; i < 8; i++)
#pragma unroll
                for (int j = 0; j < 8; j++)
                    acc[i][j] += a[i] * bb[j];
        }
        __syncthreads();
    }

#pragma unroll
    for (int i = 0; i < 8; i++) {
        int coOff = (i < 4) ? (ty * 4 + i) : (64 + ty * 4 + i - 4);
        int co = coBase + coOff;
        float bs = bias ? bias[co] : 0.f;
        float4 v0, v1;
        v0.x = acc[i][0] + bs; v0.y = acc[i][1] + bs; v0.z = acc[i][2] + bs; v0.w = acc[i][3] + bs;
        v1.x = acc[i][4] + bs; v1.y = acc[i][5] + bs; v1.z = acc[i][6] + bs; v1.w = acc[i][7] + bs;
        *(float4*)&O[(size_t)co * Npos + posBase + tx * 4]      = v0;
        *(float4*)&O[(size_t)co * Npos + posBase + 64 + tx * 4] = v1;
    }
}

// ---------------- src copy to d_out (NCHW) ----------------
__global__ void k_src_copy(float* __restrict__ out) {
    size_t idx = (size_t)blockIdx.x * 256 + threadIdx.x;   // 4,194,304
    int d  = (int)(idx >> 13);
    int ng = (int)(idx & 8191);
    int b  = ng >> 10;
    int n  = ng & 1023;
    out[SRC_OFF + ((size_t)(b * 512 + d)) * 1024 + n] = g_src[idx];
}

// ---------------- ans = mean(src, HW) ----------------
__global__ void k_ans() {
    __shared__ float sh[128];
    int id = blockIdx.x;           // d*8+b
    int d = id >> 3, b = id & 7;
    const float* p = g_src + (size_t)d * 8192 + b * 1024;
    float s = 0.f;
    for (int i = threadIdx.x; i < 1024; i += 128) s += p[i];
    s = blockReduceSum(s, sh);
    if (threadIdx.x == 0) g_ans[b * 512 + d] = s * (1.f / 1024.f);
}

// ---------------- ans_vec = ans @ ln_ans_w^T + b ----------------
__global__ void k_ansvec(const float* __restrict__ w, const float* __restrict__ bias) {
    __shared__ float sh[128];
    int b = blockIdx.x >> 9;
    int d = blockIdx.x & 511;
    float s = 0.f;
    for (int c = threadIdx.x; c < 512; c += 128)
        s += g_ans[b * 512 + c] * w[(size_t)d * 512 + c];
    s = blockReduceSum(s, sh);
    if (threadIdx.x == 0) g_ansvec[b * 512 + d] = s + bias[d];
}

// ---------------- qa build + softmax*qa fold to word ----------------
__global__ void k_qa_word(const float* __restrict__ state) {
    int b = blockIdx.x, tid = threadIdx.x;
    __shared__ float sh[256];
    float* qa = g_qa + b * 1024;
    for (int i = tid; i < 1024; i += 256) {
        float v = (i < 512) ? state[b * 512 + i] : g_ansvec[b * 512 + (i - 512)];
        qa[i] = v;
    }
    __syncthreads();
    float mx = -1e30f;
    for (int i = tid; i < 1024; i += 256) mx = fmaxf(mx, qa[i]);
    sh[tid] = mx; __syncthreads();
    for (int off = 128; off; off >>= 1) { if (tid < off) sh[tid] = fmaxf(sh[tid], sh[tid + off]); __syncthreads(); }
    mx = sh[0]; __syncthreads();
    float s = 0.f;
    for (int i = tid; i < 1024; i += 256) s += expf(qa[i] - mx);
    s = blockReduceSum(s, sh);
    float inv = 1.f / s;
    for (int c = tid; c < 512; c += 256) {
        float q1 = qa[c], q2 = qa[c + 512];
        g_word[b * 512 + c] = expf(q1 - mx) * inv * q1 + expf(q2 - mx) * inv * q2;
    }
}

// ---------------- dyn weights: word @ txt_w^T + txt_b ----------------
__global__ void k_dyngemm(const float* __restrict__ w, const float* __restrict__ bias) {
    __shared__ float sh[128];
    int j = blockIdx.x, b = blockIdx.y;
    float s = 0.f;
    for (int c = threadIdx.x; c < 512; c += 128)
        s += g_word[b * 512 + c] * w[(size_t)j * 512 + c];
    s = blockReduceSum(s, sh);
    if (threadIdx.x == 0) g_dyn[b * 2305 + j] = s + bias[j];
}

// ---------------- router stage 1 ----------------
__global__ void k_router1(const float* __restrict__ w1, const float* __restrict__ b1) {
    __shared__ float sh[128];
    int i = blockIdx.x, b = blockIdx.y;
    float s = 0.f;
    for (int c = threadIdx.x; c < 1024; c += 128)
        s += g_qa[b * 1024 + c] * w1[(size_t)i * 1024 + c];
    s = blockReduceSum(s, sh);
    if (threadIdx.x == 0) { float v = s + b1[i]; g_hidden[b * 256 + i] = v > 0.f ? v : 0.f; }
}

// ---------------- router stage 2 + softmax gates ----------------
__global__ void k_gates(const float* __restrict__ w2, const float* __restrict__ b2) {
    int b = blockIdx.x, t = threadIdx.x;   // 32 threads
    float v = -1e30f;
    if (t < 8) {
        float s = b2[t];
        for (int i = 0; i < 256; i++) s += g_hidden[b * 256 + i] * w2[t * 256 + i];
        v = s;
    }
    float mx = v;
    for (int off = 4; off; off >>= 1) mx = fmaxf(mx, __shfl_xor_sync(0xffffffffu, mx, off));
    float e = (t < 8) ? expf(v - mx) : 0.f;
    float s = e;
    for (int off = 4; off; off >>= 1) s += __shfl_xor_sync(0xffffffffu, s, off);
    if (t < 8) g_gates[b * 8 + t] = e / s;
}

// ---------------- feat128 ----------------
__global__ void k_feat(const float* __restrict__ w, const float* __restrict__ bias) {
    __shared__ float sh[128];
    int f = blockIdx.x, b = blockIdx.y;
    float s = 0.f;
    for (int c = threadIdx.x; c < 512; c += 128)
        s += g_ansvec[b * 512 + c] * w[(size_t)f * 512 + c];
    s = blockReduceSum(s, sh);
    if (threadIdx.x == 0) g_feat[b * 128 + f] = s + bias[f];
}

// ---------------- expert logits ----------------
__global__ void k_logits(const float* __restrict__ ew, const float* __restrict__ eb,
                         float* __restrict__ out) {
    int b = blockIdx.x, t = threadIdx.x;   // 192 threads
    __shared__ float sh[184];
    if (t < 184) {
        int o = t >> 3, e = t & 7;
        const float* w = ew + ((size_t)e * 23 + o) * 128;
        float s = 0.f;
        for (int f = 0; f < 128; f++) s += w[f] * g_feat[b * 128 + f];
        sh[t] = g_gates[b * 8 + e] * (s + eb[e * 23 + o]);
    }
    __syncthreads();
    if (t < 23) {
        float s = 0.f;
        for (int e = 0; e < 8; e++) s += sh[t * 8 + e];
        out[LOGIT_OFF + b * 23 + t] = s;
    }
}

// ---------------- bilinear 2x upsample (half-pixel centers, edge clamp) ----------------
__global__ void k_up2x(const float* __restrict__ in, float* __restrict__ outp,
                       int Hin, int logWout) {
    size_t idx = (size_t)blockIdx.x * 256 + threadIdx.x;
    int Wout = 1 << logWout;
    int ow = (int)(idx & (Wout - 1));
    int oh = (int)((idx >> logWout) & (Wout - 1));      // square tiles: Hout==Wout
    size_t cb = idx >> (2 * logWout);
    int Win = Hin;

    float fy = oh * 0.5f - 0.25f;
    float fx = ow * 0.5f - 0.25f;
    int y0 = (int)floorf(fy); float wy = fy - y0;
    int x0 = (int)floorf(fx); float wx = fx - x0;
    int y1 = y0 + 1, x1 = x0 + 1;
    y0 = max(y0, 0); y1 = min(y1, Hin - 1);
    x0 = max(x0, 0); x1 = min(x1, Win - 1);
    const float* p = in + cb * (size_t)(Hin * Win);
    float v00 = p[y0 * Win + x0], v01 = p[y0 * Win + x1];
    float v10 = p[y1 * Win + x0], v11 = p[y1 * Win + x1];
    outp[idx] = (1.f - wy) * ((1.f - wx) * v00 + wx * v01)
              +        wy  * ((1.f - wx) * v10 + wx * v11);
}

// ---------------- batchnorm statistics (per channel over B*H*W) ----------------
__global__ void k_bnstats(const float* __restrict__ X, float* __restrict__ mv, int Npix) {
    __shared__ float ss[256];
    __shared__ float sq[256];
    int c = blockIdx.x, tid = threadIdx.x;
    const float* p = X + (size_t)c * Npix;
    float s = 0.f, q = 0.f;
    for (int i = tid; i < Npix; i += 256) { float v = p[i]; s += v; q += v * v; }
    ss[tid] = s; sq[tid] = q; __syncthreads();
    for (int off = 128; off; off >>= 1) {
        if (tid < off) { ss[tid] += ss[tid + off]; sq[tid] += sq[tid + off]; }
        __syncthreads();
    }
    if (tid == 0) {
        float m   = ss[0] / Npix;
        float var = sq[0] / Npix - m * m;
        mv[c]              = m;
        mv[gridDim.x + c]  = rsqrtf(var + 1e-5f);
    }
}

// ---------------- bn + relu apply (in place) ----------------
__global__ void k_bnrelu(float* __restrict__ X, const float* __restrict__ mv,
                         const float* __restrict__ g, const float* __restrict__ bt,
                         int shift, int Cc) {
    size_t idx = (size_t)blockIdx.x * 256 + threadIdx.x;
    int c = (int)(idx >> shift);
    float y = (X[idx] - mv[c]) * mv[Cc + c] * g[c] + bt[c];
    X[idx] = y > 0.f ? y : 0.f;
}

// ---------------- dynamic per-batch 3x3 conv -> masks ----------------
__global__ void k_dynconv(float* __restrict__ out) {
    int b  = blockIdx.x;
    int r0 = blockIdx.y * 16;
    int tid = threadIdx.x;
    __shared__ float wsh[2304];
    __shared__ float insh[18 * 128];
    for (int i = tid; i < 2304; i += 256) wsh[i] = g_dyn[b * 2305 + i];
    float bias = g_dyn[b * 2305 + 2304];
    int ow   = tid & 127;
    int half = tid >> 7;
    float acc[8];
#pragma unroll
    for (int u = 0; u < 8; u++) acc[u] = bias;

    for (int ci = 0; ci < 256; ci++) {
        __syncthreads();
        for (int i = tid; i < 18 * 128; i += 256) {
            int rr = i >> 7, cc = i & 127;
            int ih = r0 - 1 + rr;
            insh[i] = (ih >= 0 && ih < 128)
                        ? g_c3[((size_t)ci * 8 + b) * 16384 + ih * 128 + cc] : 0.f;
        }
        __syncthreads();
        const float* wp = &wsh[ci * 9];
        float w0 = wp[0], w1 = wp[1], w2 = wp[2];
        float w3 = wp[3], w4 = wp[4], w5 = wp[5];
        float w6 = wp[6], w7 = wp[7], w8 = wp[8];
#pragma unroll
        for (int u = 0; u < 8; u++) {
            int orow = half + 2 * u;
            const float* ra = &insh[orow * 128];
            const float* rb = ra + 128;
            const float* rc = rb + 128;
            float a00 = (ow > 0)   ? ra[ow - 1] : 0.f, a01 = ra[ow], a02 = (ow < 127) ? ra[ow + 1] : 0.f;
            float a10 = (ow > 0)   ? rb[ow - 1] : 0.f, a11 = rb[ow], a12 = (ow < 127) ? rb[ow + 1] : 0.f;
            float a20 = (ow > 0)   ? rc[ow - 1] : 0.f, a21 = rc[ow], a22 = (ow < 127) ? rc[ow + 1] : 0.f;
            acc[u] += a00 * w0 + a01 * w1 + a02 * w2
                    + a10 * w3 + a11 * w4 + a12 * w5
                    + a20 * w6 + a21 * w7 + a22 * w8;
        }
    }
#pragma unroll
    for (int u = 0; u < 8; u++) {
        int orow = half + 2 * u;
        out[MASK_OFF + b * 16384 + (r0 + orow) * 128 + ow] = acc[u];
    }
}

// ---------------- launch ----------------
extern "C" void kernel_launch(void* const* d_in, const int* in_sizes, int n_in,
                              void* d_out, int out_size) {
    const float* img       = (const float*)d_in[0];
    const float* state     = (const float*)d_in[2];
    const float* W_t       = (const float*)d_in[4];
    const float* conv1_w   = (const float*)d_in[7];
    const float* bn1_g     = (const float*)d_in[8];
    const float* bn1_b     = (const float*)d_in[9];
    const float* conv2_w   = (const float*)d_in[10];
    const float* bn2_g     = (const float*)d_in[11];
    const float* bn2_b     = (const float*)d_in[12];
    const float* conv3_w   = (const float*)d_in[13];
    const float* conv3_b   = (const float*)d_in[14];
    const float* txt_w     = (const float*)d_in[15];
    const float* txt_b     = (const float*)d_in[16];
    const float* ln_ans_w  = (const float*)d_in[17];
    const float* ln_ans_b  = (const float*)d_in[18];
    const float* ln_ans2_w = (const float*)d_in[19];
    const float* ln_ans2_b = (const float*)d_in[20];
    const float* router_w1 = (const float*)d_in[21];
    const float* router_b1 = (const float*)d_in[22];
    const float* router_w2 = (const float*)d_in[23];
    const float* router_b2 = (const float*)d_in[24];
    const float* experts_w = (const float*)d_in[25];
    const float* experts_b = (const float*)d_in[26];
    float* out = (float*)d_out;

    float *pX, *pSrc, *pX1, *pC1, *pX2, *pC2, *pC3, *pMv1, *pMv2;
    cudaGetSymbolAddress((void**)&pX,   g_X);
    cudaGetSymbolAddress((void**)&pSrc, g_src);
    cudaGetSymbolAddress((void**)&pX1,  g_x1);
    cudaGetSymbolAddress((void**)&pC1,  g_c1);
    cudaGetSymbolAddress((void**)&pX2,  g_x2);
    cudaGetSymbolAddress((void**)&pC2,  g_c2);
    cudaGetSymbolAddress((void**)&pC3,  g_c3);
    cudaGetSymbolAddress((void**)&pMv1, g_mv1);
    cudaGetSymbolAddress((void**)&pMv2, g_mv2);

    // src path
    k_build_x<<<16384, 256>>>(img);
    conv_gemm<1><<<dim3(64, 4), 256>>>(W_t, pX, nullptr, pSrc, 512, 1, 1, 1, 8192);
    k_src_copy<<<16384, 256>>>(out);

    // token / small path
    k_ans<<<4096, 128>>>();
    k_ansvec<<<4096, 128>>>(ln_ans_w, ln_ans_b);
    k_qa_word<<<8, 256>>>(state);
    k_dyngemm<<<dim3(2305, 8), 128>>>(txt_w, txt_b);
    k_router1<<<dim3(256, 8), 128>>>(router_w1, router_b1);
    k_gates<<<8, 32>>>(router_w2, router_b2);
    k_feat<<<dim3(128, 8), 128>>>(ln_ans2_w, ln_ans2_b);
    k_logits<<<8, 192>>>(experts_w, experts_b, out);

    // vision path
    k_up2x<<<65536, 256>>>(pSrc, pX1, 32, 6);                                   // 32 -> 64
    conv_gemm<3><<<dim3(256, 4), 256>>>(conv1_w, pX1, nullptr, pC1, 512, 64, 64, 8, 32768);
    k_bnstats<<<512, 256>>>(pC1, pMv1, 32768);
    k_bnrelu<<<65536, 256>>>(pC1, pMv1, bn1_g, bn1_b, 15, 512);
    k_up2x<<<262144, 256>>>(pC1, pX2, 64, 7);                                   // 64 -> 128
    conv_gemm<3><<<dim3(1024, 2), 256>>>(conv2_w, pX2, nullptr, pC2, 512, 128, 128, 8, 131072);
    k_bnstats<<<256, 256>>>(pC2, pMv2, 131072);
    k_bnrelu<<<131072, 256>>>(pC2, pMv2, bn2_g, bn2_b, 17, 256);
    conv_gemm<1><<<dim3(1024, 2), 256>>>(conv3_w, pC2, conv3_b, pC3, 256, 1, 1, 1, 131072);

    // dynamic conv -> masks
    k_dynconv<<<dim3(8, 8), 256>>>(out);

    (void)in_sizes; (void)n_in; (void)out_size;
}